// round 17
// baseline (speedup 1.0000x reference)
#include <cuda_runtime.h>
#include <cuda_fp16.h>
#include <cstdint>

__device__ __forceinline__ float fmasat(float a, float b) {
    float r;
    asm("fma.rn.sat.f32 %0, %1, %2, 0f00000000;" : "=f"(r) : "f"(a), "f"(b));
    return r;
}
__device__ __forceinline__ uint32_t h2u(__half2 h) {
    return *reinterpret_cast<uint32_t*>(&h);
}
// m16n8k16 row.col f32.f16.f16.f32 — D += A*B
__device__ __forceinline__ void mma16816(float d[4],
                                         uint32_t a0, uint32_t a1, uint32_t a2, uint32_t a3,
                                         uint32_t b0, uint32_t b1) {
    asm volatile(
        "mma.sync.aligned.m16n8k16.row.col.f32.f16.f16.f32 "
        "{%0,%1,%2,%3}, {%4,%5,%6,%7}, {%8,%9}, {%0,%1,%2,%3};"
        : "+f"(d[0]), "+f"(d[1]), "+f"(d[2]), "+f"(d[3])
        : "r"(a0), "r"(a1), "r"(a2), "r"(a3), "r"(b0), "r"(b1));
}
// CNOT-ring permutation
__device__ __forceinline__ int cnot_perm(int i, int r) {
    int q = i;
#pragma unroll
    for (int m = 3; m >= 0; m--) {
        int tt = (m + r) & 3;
        int cb = 1 << (3 - m), tb = 1 << (3 - tt);
        if (q & cb) q ^= tb;
    }
    return q;
}
__device__ __forceinline__ float ldclamp(const float* row, int c) {
    int cc = min(max(c, 0), 255);
    float v = row[cc];
    return (c == cc) ? v : 0.01f;
}

// ---------------------------------------------------------------------------
// HMMA (mma.sync) kernel. Block: 8 warps = 8 output rows x 256 cols.
// Warp iter: 16 px; D[16x8] per n-tile; tiles 0,1 = Re ch0-15, 2,3 = Im.
// Split-fp16: D = ah*bh + al*bh + ah*bl  (3 MMAs per tile, shared fragments).
// out[b][ch][y][x] = sat(8 * |U_ch . p|^2 / ||p||^2)
// ---------------------------------------------------------------------------
__global__ void __launch_bounds__(256, 2)
qconv_mma_kernel(const float* __restrict__ x, const float* __restrict__ w,
                 float* __restrict__ out) {
    __shared__ float sIn[10][256];
    __shared__ float2 sU[16][9];
    __shared__ float2 gates[8][4];
    __shared__ float2 sL1[16][16];
    __shared__ float2 sL2[16][16];

    const int tid  = threadIdx.x;
    const int wid  = tid >> 5;
    const int lane = tid & 31;
    const int g    = lane >> 2;   // 0..7
    const int tg   = lane & 3;    // 0..3
    const int b    = blockIdx.z;
    const int r0   = blockIdx.y * 8;
    const float* xin = x + (size_t)b * 65536;

    // ---- (1) issue input LDGs first (col = tid, rows r0-1..r0+8) ----
    float pre[10];
#pragma unroll
    for (int j = 0; j < 10; j++) {
        int ry = r0 - 1 + j;
        pre[j] = (ry >= 0 && ry < 256) ? xin[ry * 256 + tid] : 0.01f;
    }

    // ---- (2) build unitary (overlaps input latency) ----
    {
        const int i = tid >> 4, j = tid & 15;
        if (tid < 32) {
            int gg = tid >> 2, e = tid & 3;
            int bi = e >> 1, bj = e & 1;
            float phi = w[gg * 3 + 0], th = w[gg * 3 + 1], om = w[gg * 3 + 2];
            float sh, chf;
            __sincosf(0.5f * th, &sh, &chf);
            float mag, phs;
            if (!bi && !bj)      { mag =  chf; phs = -0.5f * (phi + om); }
            else if (!bi &&  bj) { mag = -sh;  phs =  0.5f * (phi - om); }
            else if ( bi && !bj) { mag =  sh;  phs = -0.5f * (phi - om); }
            else                 { mag =  chf; phs =  0.5f * (phi + om); }
            float sp, cp;
            __sincosf(phs, &sp, &cp);
            gates[gg][e] = make_float2(mag * cp, mag * sp);
        }
        __syncthreads();
        {
            float2 v1 = make_float2(1.f, 0.f), v2 = make_float2(1.f, 0.f);
#pragma unroll
            for (int wi = 0; wi < 4; wi++) {
                int bi = (i >> (3 - wi)) & 1, bj = (j >> (3 - wi)) & 1;
                float2 e1 = gates[wi][bi * 2 + bj], e2 = gates[4 + wi][bi * 2 + bj];
                v1 = make_float2(v1.x * e1.x - v1.y * e1.y, v1.x * e1.y + v1.y * e1.x);
                v2 = make_float2(v2.x * e2.x - v2.y * e2.y, v2.x * e2.y + v2.y * e2.x);
            }
            sL1[i][j] = v1;
            sL2[i][j] = v2;
        }
        __syncthreads();
        if (j < 9) {
            const int iq = cnot_perm(i, 2);
            float2 acc = make_float2(0.f, 0.f);
#pragma unroll
            for (int k = 0; k < 16; k++) {
                const int kq = cnot_perm(k, 1);
                float2 a = sL2[iq][k], bb = sL1[kq][j];
                acc.x += a.x * bb.x - a.y * bb.y;
                acc.y += a.x * bb.y + a.y * bb.x;
            }
            sU[i][j] = acc;
        }
    }
    // ---- (3) stage input to SMEM ----
#pragma unroll
    for (int j = 0; j < 10; j++) sIn[j][tid] = pre[j];
    __syncthreads();

    // ---- (4) B fragments (once, registers). n = t*8+g; k rows per tg ----
    const int kk0 = 2 * tg, kk1 = kk0 + 1;
    uint32_t Bh[4][2], Bl[4][2];
#pragma unroll
    for (int t = 0; t < 4; t++) {
        int n = t * 8 + g;                 // 0..31
        int ch = n & 15;
        bool isIm = (n >= 16);
        float v0 = isIm ? sU[ch][kk0].y : sU[ch][kk0].x;   // kk0<=6 <9 ok
        float v1 = isIm ? sU[ch][kk1].y : sU[ch][kk1].x;   // kk1<=7 <9 ok
        __half2 hh = __floats2half2_rn(v0, v1);
        float2 hf = __half22float2(hh);
        __half2 hl = __floats2half2_rn(v0 - hf.x, v1 - hf.y);
        Bh[t][0] = h2u(hh);
        Bl[t][0] = h2u(hl);
        float v8 = (tg == 0) ? (isIm ? sU[ch][8].y : sU[ch][8].x) : 0.f;
        __half2 hh8 = __floats2half2_rn(v8, 0.f);
        float2 hf8 = __half22float2(hh8);
        __half2 hl8 = __floats2half2_rn(v8 - hf8.x, 0.f);
        Bh[t][1] = h2u(hh8);
        Bl[t][1] = h2u(hl8);
    }

    // ---- per-thread tap geometry ----
    const int dr0 = kk0 / 3, dc0 = kk0 % 3 - 1;
    const int dr1 = kk1 / 3, dc1 = kk1 % 3 - 1;
    const float* rp0 = sIn[wid + dr0];
    const float* rp1 = sIn[wid + dr1];
    const float* rp8 = sIn[wid + 2];
    const bool isTg0 = (tg == 0);

    const int y = r0 + wid;
    float* obase = out + (size_t)b * 16 * 65536 + (size_t)y * 256;

    // ---- (5) mainloop: 16 segments of 16 px ----
#pragma unroll 1
    for (int seg = 0; seg < 16; seg++) {
        const int x0p = seg * 16 + g;     // pixel row g
        const int x1p = x0p + 8;          // pixel row g+8

        // taps
        float va0 = ldclamp(rp0, x0p + dc0);
        float vb0 = ldclamp(rp1, x0p + dc1);
        float va1 = ldclamp(rp0, x1p + dc0);
        float vb1 = ldclamp(rp1, x1p + dc1);
        float v80 = isTg0 ? ldclamp(rp8, x0p + 1) : 0.f;
        float v81 = isTg0 ? ldclamp(rp8, x1p + 1) : 0.f;

        // norms via quad reduce
        float s0 = fmaf(va0, va0, fmaf(vb0, vb0, v80 * v80));
        float s1 = fmaf(va1, va1, fmaf(vb1, vb1, v81 * v81));
        s0 += __shfl_xor_sync(0xFFFFFFFFu, s0, 1);
        s0 += __shfl_xor_sync(0xFFFFFFFFu, s0, 2);
        s1 += __shfl_xor_sync(0xFFFFFFFFu, s1, 1);
        s1 += __shfl_xor_sync(0xFFFFFFFFu, s1, 2);
        float inv0 = __fdividef(8.0f, fmaxf(s0, 1e-24f));
        float inv1 = __fdividef(8.0f, fmaxf(s1, 1e-24f));

        // A fragments (hi/lo split)
        __half2 h0 = __floats2half2_rn(va0, vb0);
        __half2 h1 = __floats2half2_rn(va1, vb1);
        float2 f0 = __half22float2(h0);
        float2 f1 = __half22float2(h1);
        __half2 l0 = __floats2half2_rn(va0 - f0.x, vb0 - f0.y);
        __half2 l1 = __floats2half2_rn(va1 - f1.x, vb1 - f1.y);
        uint32_t a0h = h2u(h0), a1h = h2u(h1);
        uint32_t a0l = h2u(l0), a1l = h2u(l1);
        uint32_t a2h = 0, a3h = 0, a2l = 0, a3l = 0;
        if (isTg0) {
            __half2 h8a = __floats2half2_rn(v80, 0.f);
            __half2 h8b = __floats2half2_rn(v81, 0.f);
            float2 f8a = __half22float2(h8a);
            float2 f8b = __half22float2(h8b);
            a2h = h2u(h8a);
            a3h = h2u(h8b);
            a2l = h2u(__floats2half2_rn(v80 - f8a.x, 0.f));
            a3l = h2u(__floats2half2_rn(v81 - f8b.x, 0.f));
        }

        // accumulate 4 n-tiles x 3 split terms
        float d[4][4];
#pragma unroll
        for (int t = 0; t < 4; t++)
#pragma unroll
            for (int i = 0; i < 4; i++) d[t][i] = 0.f;

#pragma unroll
        for (int t = 0; t < 4; t++) {
            mma16816(d[t], a0h, a1h, a2h, a3h, Bh[t][0], Bh[t][1]);
            mma16816(d[t], a0l, a1l, a2l, a3l, Bh[t][0], Bh[t][1]);
            mma16816(d[t], a0h, a1h, a2h, a3h, Bl[t][0], Bl[t][1]);
        }

        // epilogue: re from tile t, im from tile t+2 (same thread, same slot)
#pragma unroll
        for (int t = 0; t < 2; t++) {
            float* oc = obase + (size_t)(t * 8 + kk0) * 65536;
            float m;
            m = fmaf(d[t + 2][0], d[t + 2][0], d[t][0] * d[t][0]);
            oc[x0p] = fmasat(m, inv0);
            m = fmaf(d[t + 2][1], d[t + 2][1], d[t][1] * d[t][1]);
            oc[65536 + x0p] = fmasat(m, inv0);
            m = fmaf(d[t + 2][2], d[t + 2][2], d[t][2] * d[t][2]);
            oc[x1p] = fmasat(m, inv1);
            m = fmaf(d[t + 2][3], d[t + 2][3], d[t][3] * d[t][3]);
            oc[65536 + x1p] = fmasat(m, inv1);
        }
    }
}

extern "C" void kernel_launch(void* const* d_in, const int* in_sizes, int n_in,
                              void* d_out, int out_size) {
    const float* x = (const float*)d_in[0];        // (32,1,256,256) fp32
    const float* w = (const float*)d_in[1];        // (2,4,3) fp32
    float* out = (float*)d_out;                    // (32,16,256,256) fp32

    dim3 block(256, 1, 1);
    dim3 grid(1, 32, 32);
    qconv_mma_kernel<<<grid, block>>>(x, w, out);
}